// round 12
// baseline (speedup 1.0000x reference)
#include <cuda_runtime.h>
#include <cuda_bf16.h>

// ---------------------------------------------------------------------------
// Problem constants
// ---------------------------------------------------------------------------
#define B_   64
#define T_   50
#define E_   1024
#define H_   1024
#define NI_  32000
#define KK_  4
#define WW_  32
#define NN_  10
#define LOUT_ 993           // H - W + 1
#define M_   (B_ * T_)      // 3200 rows
#define F_   (NN_ + 2 * H_) // 2058 features into final linear
#define FPAD_ 2064          // F_ padded up to multiple of 16

// ---------------------------------------------------------------------------
// Device scratch (static, no runtime allocation)
// ---------------------------------------------------------------------------
__device__ float g_XUI[M_ * 2 * E_];          // [u | it] gathered, 3200 x 2048
__device__ float g_attpre[M_ * E_];           // 3200 x 1024
__device__ float g_WA[E_ * 4096];             // [Wh | W_hh^T], 1024 x 4096
__device__ float g_WIT[2 * E_ * 3 * H_];      // W_ih^T, 2048 x 3072
__device__ float g_h[B_ * H_];                // current hidden state
__device__ float g_gh[B_ * 3 * H_];           // h @ W_hh^T + b_hh
__device__ float g_x[B_ * 2 * E_];            // [att*u, (1-att)*it]
__device__ float g_gi[B_ * 3 * H_];           // x @ W_ih^T + b_ih
__device__ float g_buf[KK_ * B_ * H_];        // ring buffer of last K hidden states
__device__ float g_ful[M_ * FPAD_];           // concat(v, h, l) per (b,t), padded

// ---------------------------------------------------------------------------
// Init: zero h, ring buffer, and the pad columns of ful
// ---------------------------------------------------------------------------
__global__ void init_kernel() {
    const int n1 = B_ * H_;
    const int n2 = KK_ * B_ * H_;
    const int n3 = M_ * (FPAD_ - F_);
    const int tot = n1 + n2 + n3;
    for (int i = blockIdx.x * blockDim.x + threadIdx.x; i < tot;
         i += gridDim.x * blockDim.x) {
        if (i < n1)           g_h[i] = 0.f;
        else if (i < n1 + n2) g_buf[i - n1] = 0.f;
        else {
            int k = i - n1 - n2;
            int row = k / (FPAD_ - F_);
            int c = k % (FPAD_ - F_);
            g_ful[row * FPAD_ + F_ + c] = 0.f;
        }
    }
}

// ---------------------------------------------------------------------------
// Prep: build WA = [Wh | W_hh^T] (1024x4096) and WIT = W_ih^T (2048x3072)
// ---------------------------------------------------------------------------
__global__ void prep_kernel(const float* __restrict__ att_W,
                            const float* __restrict__ W_hh,
                            const float* __restrict__ W_ih) {
    const int tot1 = E_ * 4096;
    const int tot2 = 2 * E_ * 3 * H_;
    for (int i = blockIdx.x * blockDim.x + threadIdx.x; i < tot1 + tot2;
         i += gridDim.x * blockDim.x) {
        if (i < tot1) {
            int e = i >> 12;       // / 4096
            int f = i & 4095;
            g_WA[i] = (f < H_) ? att_W[(2 * E_ + e) * E_ + f]
                               : W_hh[(f - H_) * H_ + e];
        } else {
            int k = i - tot1;
            int e = k / (3 * H_);
            int j = k % (3 * H_);
            g_WIT[k] = W_ih[j * (2 * E_) + e];
        }
    }
}

// ---------------------------------------------------------------------------
// Gather: XUI[bt] = [user_emb[uv[bt]], item_emb[iv[bt]]]
// ---------------------------------------------------------------------------
__global__ void gather_kernel(const int* __restrict__ uv,
                              const int* __restrict__ iv,
                              const float* __restrict__ ue,
                              const float* __restrict__ ie) {
    const int tot = M_ * E_;
    for (int i = blockIdx.x * blockDim.x + threadIdx.x; i < tot;
         i += gridDim.x * blockDim.x) {
        int bt = i >> 10;
        int e = i & 1023;
        g_XUI[bt * 2048 + e]        = ue[(size_t)uv[bt] * E_ + e];
        g_XUI[bt * 2048 + 1024 + e] = ie[(size_t)iv[bt] * E_ + e];
    }
}

// ---------------------------------------------------------------------------
// Big GEMM: C = A @ B + bias(col). 128x128 tile, BK=16, 8x8 per thread.
// MODE 0: attpre = XUI(3200x2048) @ Batt(2048x1024), C -> g_attpre
// MODE 1: logits = ful(3200x2058 pad 2064) @ lin_W(2058x32000), C -> arg
// ---------------------------------------------------------------------------
template <int MODE>
__global__ __launch_bounds__(256)
void big_gemm_kernel(const float* __restrict__ Bm,
                     const float* __restrict__ bias,
                     float* __restrict__ Carg) {
    constexpr int KD  = (MODE == 0) ? 2048 : 2058;
    constexpr int LDA = (MODE == 0) ? 2048 : FPAD_;
    constexpr int LDB = (MODE == 0) ? 1024 : NI_;
    constexpr int LDC = (MODE == 0) ? 1024 : NI_;
    const float* A = (MODE == 0) ? g_XUI : g_ful;
    float* C = (MODE == 0) ? g_attpre : Carg;

    __shared__ float As[16][128];
    __shared__ float Bs[16][128];

    const int tid = threadIdx.x;
    const int m0 = blockIdx.y * 128;
    const int n0 = blockIdx.x * 128;
    const int tx = tid & 15;
    const int ty = tid >> 4;

    float acc[8][8];
#pragma unroll
    for (int i = 0; i < 8; i++)
#pragma unroll
        for (int j = 0; j < 8; j++) acc[i][j] = 0.f;

    const int nk = (KD + 15) / 16;
    for (int kt = 0; kt < nk; kt++) {
        const int kb = kt * 16;
        // A tile: 128 rows x 16 cols -> 512 float4, 2 per thread
#pragma unroll
        for (int i = 0; i < 2; i++) {
            int idx = tid + i * 256;
            int r = idx >> 2;
            int c4 = (idx & 3) * 4;
            float4 v;
            if (kb + c4 + 3 < KD) {
                v = *reinterpret_cast<const float4*>(&A[(size_t)(m0 + r) * LDA + kb + c4]);
            } else {
                v.x = (kb + c4 + 0 < KD) ? A[(size_t)(m0 + r) * LDA + kb + c4 + 0] : 0.f;
                v.y = (kb + c4 + 1 < KD) ? A[(size_t)(m0 + r) * LDA + kb + c4 + 1] : 0.f;
                v.z = (kb + c4 + 2 < KD) ? A[(size_t)(m0 + r) * LDA + kb + c4 + 2] : 0.f;
                v.w = 0.f;
            }
            As[c4 + 0][r] = v.x; As[c4 + 1][r] = v.y;
            As[c4 + 2][r] = v.z; As[c4 + 3][r] = v.w;
        }
        // B tile: 16 rows x 128 cols -> 512 float4, 2 per thread
#pragma unroll
        for (int i = 0; i < 2; i++) {
            int idx = tid + i * 256;
            int r = idx >> 5;
            int c4 = (idx & 31) * 4;
            float4 v = make_float4(0.f, 0.f, 0.f, 0.f);
            if (kb + r < KD)
                v = *reinterpret_cast<const float4*>(&Bm[(size_t)(kb + r) * LDB + n0 + c4]);
            *reinterpret_cast<float4*>(&Bs[r][c4]) = v;
        }
        __syncthreads();
#pragma unroll
        for (int k = 0; k < 16; k++) {
            float ra[8], rb[8];
            *reinterpret_cast<float4*>(ra)     = *reinterpret_cast<const float4*>(&As[k][ty * 8]);
            *reinterpret_cast<float4*>(ra + 4) = *reinterpret_cast<const float4*>(&As[k][ty * 8 + 4]);
            *reinterpret_cast<float4*>(rb)     = *reinterpret_cast<const float4*>(&Bs[k][tx * 8]);
            *reinterpret_cast<float4*>(rb + 4) = *reinterpret_cast<const float4*>(&Bs[k][tx * 8 + 4]);
#pragma unroll
            for (int i = 0; i < 8; i++)
#pragma unroll
                for (int j = 0; j < 8; j++) acc[i][j] += ra[i] * rb[j];
        }
        __syncthreads();
    }

#pragma unroll
    for (int i = 0; i < 8; i++) {
        int row = m0 + ty * 8 + i;
#pragma unroll
        for (int j = 0; j < 8; j += 4) {
            int col = n0 + tx * 8 + j;
            float4 v;
            v.x = acc[i][j + 0] + bias[col + 0];
            v.y = acc[i][j + 1] + bias[col + 1];
            v.z = acc[i][j + 2] + bias[col + 2];
            v.w = acc[i][j + 3] + bias[col + 3];
            *reinterpret_cast<float4*>(&C[(size_t)row * LDC + col]) = v;
        }
    }
}

// ---------------------------------------------------------------------------
// Small-M GEMM (M=64) for the scan, 64x32 tile, BK=32, 4x2 per thread.
// MODE 0 (phase1): C = h @ WA (K=1024, N=4096). Epilogue:
//   cols <1024: att = sigmoid(attpre + c); g_x = [att*u, (1-att)*it]
//   cols >=1024: g_gh = c + b_hh
// MODE 1 (phase2): C = x @ WIT (K=2048, N=3072). Epilogue: g_gi = c + b_ih
// ---------------------------------------------------------------------------
template <int MODE>
__global__ __launch_bounds__(256)
void small_gemm_kernel(int t, const float* __restrict__ bias) {
    constexpr int KD  = (MODE == 0) ? 1024 : 2048;
    constexpr int LDB = (MODE == 0) ? 4096 : 3072;
    const float* A = (MODE == 0) ? g_h : g_x;
    const float* Bm = (MODE == 0) ? g_WA : g_WIT;

    __shared__ float As[32][64];
    __shared__ float Bs[32][32];

    const int tid = threadIdx.x;
    const int n0 = blockIdx.x * 32;
    const int tx = tid & 15;
    const int ty = tid >> 4;

    float acc[4][2] = {{0.f, 0.f}, {0.f, 0.f}, {0.f, 0.f}, {0.f, 0.f}};

    for (int kb = 0; kb < KD; kb += 32) {
        // A tile 64x32: 512 float4, 2 per thread
#pragma unroll
        for (int i = 0; i < 2; i++) {
            int idx = tid + i * 256;
            int r = idx >> 3;
            int c4 = (idx & 7) * 4;
            float4 v = *reinterpret_cast<const float4*>(&A[r * KD + kb + c4]);
            As[c4 + 0][r] = v.x; As[c4 + 1][r] = v.y;
            As[c4 + 2][r] = v.z; As[c4 + 3][r] = v.w;
        }
        // B tile 32x32: 256 float4, 1 per thread
        {
            int r = tid >> 3;
            int c4 = (tid & 7) * 4;
            *reinterpret_cast<float4*>(&Bs[r][c4]) =
                *reinterpret_cast<const float4*>(&Bm[(kb + r) * LDB + n0 + c4]);
        }
        __syncthreads();
#pragma unroll
        for (int k = 0; k < 32; k++) {
            float4 a = *reinterpret_cast<const float4*>(&As[k][ty * 4]);
            float2 bv = *reinterpret_cast<const float2*>(&Bs[k][tx * 2]);
            acc[0][0] += a.x * bv.x; acc[0][1] += a.x * bv.y;
            acc[1][0] += a.y * bv.x; acc[1][1] += a.y * bv.y;
            acc[2][0] += a.z * bv.x; acc[2][1] += a.z * bv.y;
            acc[3][0] += a.w * bv.x; acc[3][1] += a.w * bv.y;
        }
        __syncthreads();
    }

#pragma unroll
    for (int i = 0; i < 4; i++) {
        int b = ty * 4 + i;
#pragma unroll
        for (int j = 0; j < 2; j++) {
            int f = n0 + tx * 2 + j;
            float c = acc[i][j];
            if (MODE == 0) {
                if (f < 1024) {
                    int row = b * T_ + t;
                    float a = 1.f / (1.f + __expf(-(g_attpre[row * E_ + f] + c)));
                    g_x[b * 2048 + f]        = a * g_XUI[row * 2048 + f];
                    g_x[b * 2048 + 1024 + f] = (1.f - a) * g_XUI[row * 2048 + 1024 + f];
                } else {
                    int j2 = f - 1024;
                    g_gh[b * 3072 + j2] = c + bias[j2];
                }
            } else {
                g_gi[b * 3072 + f] = c + bias[f];
            }
        }
    }
}

// ---------------------------------------------------------------------------
// GRU update + sliding-window cov (v) + vertical cov (q, l) + write ful row.
// One block per batch element.
// ---------------------------------------------------------------------------
__global__ __launch_bounds__(256)
void gru_step_kernel(int t,
                     const float* __restrict__ hcov_W,
                     const float* __restrict__ hcov_b,
                     const float* __restrict__ vcov_W,
                     const float* __restrict__ vcov_b) {
    const int b = blockIdx.x;
    const int tid = threadIdx.x;
    __shared__ float hnew[H_];
    __shared__ float cs[WW_];
    __shared__ float rbuf[8];

    const float vw0 = vcov_W[0], vw1 = vcov_W[1], vw2 = vcov_W[2], vw3 = vcov_W[3];
    const float vb = vcov_b[0];
    const int row = b * T_ + t;
    const int slot = t & 3;

    for (int j = tid; j < H_; j += 256) {
        float hold = g_h[b * H_ + j];
        float gir = g_gi[b * 3072 + j];
        float giz = g_gi[b * 3072 + 1024 + j];
        float gin = g_gi[b * 3072 + 2048 + j];
        float ghr = g_gh[b * 3072 + j];
        float ghz = g_gh[b * 3072 + 1024 + j];
        float ghn = g_gh[b * 3072 + 2048 + j];
        float r = 1.f / (1.f + __expf(-(gir + ghr)));
        float z = 1.f / (1.f + __expf(-(giz + ghz)));
        float n = tanhf(gin + r * ghn);
        float hn = (1.f - z) * n + z * hold;
        hnew[j] = hn;
        g_h[b * H_ + j] = hn;
        g_buf[slot * (B_ * H_) + b * H_ + j] = hn;
        float l = 0.f;
        if (t >= KK_ - 1) {
            float q = vw0 * g_buf[((t + 1) & 3) * (B_ * H_) + b * H_ + j]
                    + vw1 * g_buf[((t + 2) & 3) * (B_ * H_) + b * H_ + j]
                    + vw2 * g_buf[((t + 3) & 3) * (B_ * H_) + b * H_ + j]
                    + vw3 * hn + vb;
            l = hn * q;
        }
        g_ful[row * FPAD_ + NN_ + j] = hn;
        g_ful[row * FPAD_ + NN_ + H_ + j] = l;
    }
    __syncthreads();

    // sum of hnew[0 .. Lout-1] (993 elements)
    float s = 0.f;
    for (int j = tid; j < LOUT_; j += 256) s += hnew[j];
#pragma unroll
    for (int o = 16; o > 0; o >>= 1) s += __shfl_down_sync(0xffffffffu, s, o);
    if ((tid & 31) == 0) rbuf[tid >> 5] = s;
    __syncthreads();
    if (tid == 0) {
        float S = 0.f;
#pragma unroll
        for (int w = 0; w < 8; w++) S += rbuf[w];
        cs[0] = S;
        for (int j = 1; j < WW_; j++)
            cs[j] = cs[j - 1] - hnew[j - 1] + hnew[LOUT_ - 1 + j];
    }
    __syncthreads();
    if (tid < NN_) {
        float v = hcov_b[tid] * (float)LOUT_;
#pragma unroll
        for (int jj = 0; jj < WW_; jj++) v += hcov_W[tid * WW_ + jj] * cs[jj];
        g_ful[row * FPAD_ + tid] = v;
    }
}

// ---------------------------------------------------------------------------
// In-place log-softmax over NI columns, one block per row.
// ---------------------------------------------------------------------------
__global__ __launch_bounds__(512)
void logsoftmax_kernel(float* __restrict__ out) {
    const int row = blockIdx.x;
    float* p = out + (size_t)row * NI_;
    const int tid = threadIdx.x;

    float m = -1e30f, s = 0.f;
    for (int c = tid; c < NI_; c += 512) {
        float v = p[c];
        if (v > m) { s = s * __expf(m - v) + 1.f; m = v; }
        else        s += __expf(v - m);
    }
#pragma unroll
    for (int o = 16; o > 0; o >>= 1) {
        float m2 = __shfl_down_sync(0xffffffffu, m, o);
        float s2 = __shfl_down_sync(0xffffffffu, s, o);
        float M = fmaxf(m, m2);
        s = s * __expf(m - M) + s2 * __expf(m2 - M);
        m = M;
    }
    __shared__ float sm[16], ss[16];
    __shared__ float off;
    if ((tid & 31) == 0) { sm[tid >> 5] = m; ss[tid >> 5] = s; }
    __syncthreads();
    if (tid == 0) {
        float M = sm[0], S = ss[0];
        for (int w = 1; w < 16; w++) {
            float m2 = sm[w], s2 = ss[w];
            float MM = fmaxf(M, m2);
            S = S * __expf(M - MM) + s2 * __expf(m2 - MM);
            M = MM;
        }
        off = M + logf(S);
    }
    __syncthreads();
    float o2 = off;
    for (int c = tid; c < NI_; c += 512) p[c] -= o2;
}

// ---------------------------------------------------------------------------
// Launch
// ---------------------------------------------------------------------------
extern "C" void kernel_launch(void* const* d_in, const int* in_sizes, int n_in,
                              void* d_out, int out_size) {
    (void)in_sizes; (void)n_in; (void)out_size;
    const int*   uv       = (const int*)d_in[0];
    const int*   iv       = (const int*)d_in[1];
    const float* user_emb = (const float*)d_in[2];
    const float* item_emb = (const float*)d_in[3];
    const float* att_W    = (const float*)d_in[4];
    const float* att_b    = (const float*)d_in[5];
    const float* W_ih     = (const float*)d_in[6];
    const float* b_ih     = (const float*)d_in[7];
    const float* W_hh     = (const float*)d_in[8];
    const float* b_hh     = (const float*)d_in[9];
    const float* hcov_W   = (const float*)d_in[10];
    const float* hcov_b   = (const float*)d_in[11];
    const float* vcov_W   = (const float*)d_in[12];
    const float* vcov_b   = (const float*)d_in[13];
    const float* lin_W    = (const float*)d_in[14];
    const float* lin_b    = (const float*)d_in[15];
    float* out = (float*)d_out;

    init_kernel<<<256, 256>>>();
    prep_kernel<<<2048, 256>>>(att_W, W_hh, W_ih);
    gather_kernel<<<2048, 256>>>(uv, iv, user_emb, item_emb);

    {   // att_pre = XUI @ att_W[:2048] + att_b
        dim3 grid(E_ / 128, M_ / 128);
        big_gemm_kernel<0><<<grid, 256>>>(att_W, att_b, nullptr);
    }

    for (int t = 0; t < T_; t++) {
        small_gemm_kernel<0><<<4096 / 32, 256>>>(t, b_hh);   // h@[Wh|W_hh^T], att, x
        small_gemm_kernel<1><<<3072 / 32, 256>>>(t, b_ih);   // gi = x@W_ih^T
        gru_step_kernel<<<B_, 256>>>(t, hcov_W, hcov_b, vcov_W, vcov_b);
    }

    {   // logits = ful @ lin_W + lin_b  -> d_out
        dim3 grid(NI_ / 128, M_ / 128);
        big_gemm_kernel<1><<<grid, 256>>>(lin_W, lin_b, out);
    }

    logsoftmax_kernel<<<M_, 512>>>(out);
}